// round 16
// baseline (speedup 1.0000x reference)
#include <cuda_runtime.h>
#include <cuda_fp16.h>
#include <mma.h>
#include <cstdint>

using namespace nvcuda;

#define N_NODES 100000
#define N_EDGES 1600000
#define D 64
#define NPAD 100096           // 782 * 128, padded node count
#define SCAN_NB 98            // ceil(100000/1024)

// ---------------- static scratch (device-code access ONLY — never passed from host) ----
// Zero-initialized at load; k_tail restores g_deg_i's zeros each launch.
__device__ int   g_deg_i[N_NODES];
__device__ int   g_bsum[128];             // block totals (overwritten every run)
__device__ int   g_rp[N_NODES + 1];       // CSR row pointers (by dst)
__device__ int   g_epos[N_EDGES];         // per-edge within-dst position
__device__ int   g_col[N_EDGES];          // CSR column (src) indices
__device__ float g_inv[N_NODES];
__device__ __align__(16) __half g_xlh [NPAD * D];  // layer-1: x @ W1l^T, fp16 (gathered)
__device__ __align__(16) float  g_p   [NPAD * D];  // layer-1: x @ W1r^T + b1 (fp32)
__device__ __align__(16) __half g_xl2h[NPAD * D];  // layer-2: h @ W2l^T, fp16 (gathered)
__device__ __align__(16) float  g_p2  [NPAD * D];  // layer-2: h @ W2r^T + b2 (fp32)

// ---------------- CSR build (round-14 proven versions) ----------------

// Degree count + per-edge slot assignment (atomic return value = position).
__global__ void k_pos(const int* __restrict__ dst) {
    int i = blockIdx.x * blockDim.x + threadIdx.x;
    if (i < N_EDGES / 2) {
        const int2 d = reinterpret_cast<const int2*>(dst)[i];
        const int p0 = atomicAdd(&g_deg_i[d.x], 1);
        const int p1 = atomicAdd(&g_deg_i[d.y], 1);
        reinterpret_cast<int2*>(g_epos)[i] = make_int2(p0, p1);
    }
}

// Block-level inclusive scan (1024 wide); writes rp[i+1] (partial) + block totals.
__global__ __launch_bounds__(1024) void k_scan1() {
    __shared__ int s[1024];
    const int t = threadIdx.x, b = blockIdx.x;
    const int i = b * 1024 + t;
    s[t] = (i < N_NODES) ? g_deg_i[i] : 0;
    __syncthreads();
    for (int off = 1; off < 1024; off <<= 1) {
        int u = (t >= off) ? s[t - off] : 0;
        __syncthreads();
        s[t] += u;
        __syncthreads();
    }
    if (i < N_NODES) g_rp[i + 1] = s[t];
    if (t == 1023) g_bsum[b] = s[t];
}

// Finalize rp (adding inline prefix of block sums, smem-staged) + inv_deg.
__global__ void k_scan3() {
    __shared__ int sb[128];
    const int t = threadIdx.x;
    if (t < 128) sb[t] = g_bsum[t];
    __syncthreads();
    int i = blockIdx.x * blockDim.x + t;
    if (i < N_NODES) {
        const int b = i >> 10;
        int off = 0;
        for (int j = 0; j < b; j++) off += sb[j];   // <=97 smem adds
        g_rp[i + 1] += off;
        g_inv[i] = 1.0f / (float)max(g_deg_i[i], 1);
    }
    if (i == 0) g_rp[0] = 0;
}

// Atomic-free fill: slot = rp[dst] + epos[e].
__global__ void k_fill(const int* __restrict__ src, const int* __restrict__ dst) {
    int i = blockIdx.x * blockDim.x + threadIdx.x;
    if (i < N_EDGES / 2) {
        const int2 s = reinterpret_cast<const int2*>(src)[i];
        const int2 d = reinterpret_cast<const int2*>(dst)[i];
        const int2 p = reinterpret_cast<const int2*>(g_epos)[i];
        g_col[g_rp[d.x] + p.x] = s.x;
        g_col[g_rp[d.y] + p.y] = s.y;
    }
}

// Tail: restore zeroed g_deg_i for the next replay (off the critical path).
__global__ void k_tail() {
    int i = blockIdx.x * blockDim.x + threadIdx.x;
    if (i < N_NODES) g_deg_i[i] = 0;
}

// ---------------- layer-1 tensor-core dual GEMM ----------------
// xl = x @ W1l^T (fp16 -> g_xlh),  p = x @ W1r^T + b1 (fp32 -> g_p).
__global__ __launch_bounds__(256) void k_gemm1(const float* __restrict__ xin,
                                               const float* __restrict__ Wl,
                                               const float* __restrict__ Wr,
                                               const float* __restrict__ bia) {
    __shared__ __half sw[128 * 72];        // weights: rows 0-63 Wl, 64-127 Wr
    __shared__ __half sx[128 * 72];        // input tile (128 nodes)
    __shared__ float  stage[8][256];       // per-warp 16x16 epilogue staging

    const int tid = threadIdx.x;
    const int rbase = blockIdx.x * 128;

    #pragma unroll
    for (int i = tid; i < 128 * 64; i += 256) {
        const int o = i >> 6, k = i & 63;
        const float w = (o < 64) ? Wl[o * 64 + k] : Wr[(o - 64) * 64 + k];
        sw[o * 72 + k] = __float2half(w);
    }
    #pragma unroll
    for (int i = tid; i < 128 * 32; i += 256) {    // float2 chunks, convert inline
        const int r = i >> 5, c2 = i & 31;
        const int gn = rbase + r;
        float2 v = make_float2(0.f, 0.f);
        if (gn < N_NODES) v = reinterpret_cast<const float2*>(xin)[gn * 32 + c2];
        *reinterpret_cast<__half2*>(&sx[r * 72 + c2 * 2]) = __floats2half2_rn(v.x, v.y);
    }
    __syncthreads();

    const int warp = tid >> 5;
    const int lane = tid & 31;

    wmma::fragment<wmma::accumulator, 16, 16, 16, float> c[8];
    #pragma unroll
    for (int i = 0; i < 8; i++) wmma::fill_fragment(c[i], 0.f);

    #pragma unroll
    for (int kk = 0; kk < 4; kk++) {
        wmma::fragment<wmma::matrix_a, 16, 16, 16, __half, wmma::row_major> a;
        wmma::load_matrix_sync(a, &sx[warp * 16 * 72 + kk * 16], 72);
        #pragma unroll
        for (int ct = 0; ct < 8; ct++) {
            wmma::fragment<wmma::matrix_b, 16, 16, 16, __half, wmma::col_major> bf;
            wmma::load_matrix_sync(bf, &sw[(ct * 16) * 72 + kk * 16], 72);
            wmma::mma_sync(c[ct], a, bf, c[ct]);
        }
    }

    #pragma unroll
    for (int ct = 0; ct < 8; ct++) {
        wmma::store_matrix_sync(stage[warp], c[ct], 16, wmma::mem_row_major);
        __syncwarp();
        const int r  = lane >> 1;
        const int cc = (lane & 1) * 8;
        const float* sp = &stage[warp][r * 16 + cc];
        const int gn = rbase + warp * 16 + r;
        if (ct < 4) {
            const int col = ct * 16 + cc;
            __half2 h0 = __floats2half2_rn(sp[0], sp[1]);
            __half2 h1 = __floats2half2_rn(sp[2], sp[3]);
            __half2 h2 = __floats2half2_rn(sp[4], sp[5]);
            __half2 h3 = __floats2half2_rn(sp[6], sp[7]);
            uint4 pk;
            pk.x = *reinterpret_cast<uint32_t*>(&h0);
            pk.y = *reinterpret_cast<uint32_t*>(&h1);
            pk.z = *reinterpret_cast<uint32_t*>(&h2);
            pk.w = *reinterpret_cast<uint32_t*>(&h3);
            *reinterpret_cast<uint4*>(&g_xlh[gn * D + col]) = pk;
        } else {
            const int col = (ct - 4) * 16 + cc;
            float4 o0 = make_float4(sp[0] + bia[col + 0], sp[1] + bia[col + 1],
                                    sp[2] + bia[col + 2], sp[3] + bia[col + 3]);
            float4 o1 = make_float4(sp[4] + bia[col + 4], sp[5] + bia[col + 5],
                                    sp[6] + bia[col + 6], sp[7] + bia[col + 7]);
            *reinterpret_cast<float4*>(&g_p[gn * D + col + 0]) = o0;
            *reinterpret_cast<float4*>(&g_p[gn * D + col + 4]) = o1;
        }
        __syncwarp();
    }
}

// ---------------- fused layer-1 aggregation + layer-2 GEMM ----------------
// Phase A: h[node] = relu(mean_agg(g_xlh) + g_p[node]) -> sx (fp16, smem only).
// Phase B: xl2 = h @ W2l^T (fp16 -> g_xl2h), p2 = h @ W2r^T + b2 (fp32 -> g_p2).
// Separate output buffers: other blocks still read g_xlh/g_p during phase A.
__global__ __launch_bounds__(256) void k_ag2(const float* __restrict__ Wl,
                                             const float* __restrict__ Wr,
                                             const float* __restrict__ bia) {
    __shared__ __half sw[128 * 72];
    __shared__ __half sx[128 * 72];
    __shared__ float  stage[8][256];

    const int tid = threadIdx.x;
    const int rbase = blockIdx.x * 128;
    const int warp = tid >> 5;
    const int lane = tid & 31;

    #pragma unroll
    for (int i = tid; i < 128 * 64; i += 256) {
        const int o = i >> 6, k = i & 63;
        const float w = (o < 64) ? Wl[o * 64 + k] : Wr[(o - 64) * 64 + k];
        sw[o * 72 + k] = __float2half(w);
    }

    // Phase A: each warp aggregates 16 nodes (lane owns cols 2*lane, 2*lane+1).
    const __half2* xl = reinterpret_cast<const __half2*>(g_xlh);
    for (int nn = warp; nn < 128; nn += 8) {
        const int node = rbase + nn;
        __half2 hv = __float2half2_rn(0.f);
        if (node < N_NODES) {
            const int s0 = g_rp[node], s1 = g_rp[node + 1];
            float2 acc = make_float2(0.f, 0.f);
            int j = s0;
            for (; j + 7 < s1; j += 8) {
                int n[8];
                #pragma unroll
                for (int u = 0; u < 8; u++) n[u] = g_col[j + u];
                float2 v[8];
                #pragma unroll
                for (int u = 0; u < 8; u++) v[u] = __half22float2(xl[n[u] * 32 + lane]);
                acc.x += ((v[0].x + v[1].x) + (v[2].x + v[3].x)) + ((v[4].x + v[5].x) + (v[6].x + v[7].x));
                acc.y += ((v[0].y + v[1].y) + (v[2].y + v[3].y)) + ((v[4].y + v[5].y) + (v[6].y + v[7].y));
            }
            for (; j < s1; j++) {
                const float2 v = __half22float2(xl[g_col[j] * 32 + lane]);
                acc.x += v.x; acc.y += v.y;
            }
            const float inv = g_inv[node];
            const float2 pp = reinterpret_cast<const float2*>(g_p)[node * 32 + lane];
            const float rx = fmaxf(fmaf(acc.x, inv, pp.x), 0.f);
            const float ry = fmaxf(fmaf(acc.y, inv, pp.y), 0.f);
            hv = __floats2half2_rn(rx, ry);
        }
        *reinterpret_cast<__half2*>(&sx[nn * 72 + lane * 2]) = hv;
    }
    __syncthreads();

    // Phase B: GEMM identical to layer-1 structure.
    wmma::fragment<wmma::accumulator, 16, 16, 16, float> c[8];
    #pragma unroll
    for (int i = 0; i < 8; i++) wmma::fill_fragment(c[i], 0.f);

    #pragma unroll
    for (int kk = 0; kk < 4; kk++) {
        wmma::fragment<wmma::matrix_a, 16, 16, 16, __half, wmma::row_major> a;
        wmma::load_matrix_sync(a, &sx[warp * 16 * 72 + kk * 16], 72);
        #pragma unroll
        for (int ct = 0; ct < 8; ct++) {
            wmma::fragment<wmma::matrix_b, 16, 16, 16, __half, wmma::col_major> bf;
            wmma::load_matrix_sync(bf, &sw[(ct * 16) * 72 + kk * 16], 72);
            wmma::mma_sync(c[ct], a, bf, c[ct]);
        }
    }

    #pragma unroll
    for (int ct = 0; ct < 8; ct++) {
        wmma::store_matrix_sync(stage[warp], c[ct], 16, wmma::mem_row_major);
        __syncwarp();
        const int r  = lane >> 1;
        const int cc = (lane & 1) * 8;
        const float* sp = &stage[warp][r * 16 + cc];
        const int gn = rbase + warp * 16 + r;
        if (ct < 4) {
            const int col = ct * 16 + cc;
            __half2 h0 = __floats2half2_rn(sp[0], sp[1]);
            __half2 h1 = __floats2half2_rn(sp[2], sp[3]);
            __half2 h2 = __floats2half2_rn(sp[4], sp[5]);
            __half2 h3 = __floats2half2_rn(sp[6], sp[7]);
            uint4 pk;
            pk.x = *reinterpret_cast<uint32_t*>(&h0);
            pk.y = *reinterpret_cast<uint32_t*>(&h1);
            pk.z = *reinterpret_cast<uint32_t*>(&h2);
            pk.w = *reinterpret_cast<uint32_t*>(&h3);
            *reinterpret_cast<uint4*>(&g_xl2h[gn * D + col]) = pk;
        } else {
            const int col = (ct - 4) * 16 + cc;
            float4 o0 = make_float4(sp[0] + bia[col + 0], sp[1] + bia[col + 1],
                                    sp[2] + bia[col + 2], sp[3] + bia[col + 3]);
            float4 o1 = make_float4(sp[4] + bia[col + 4], sp[5] + bia[col + 5],
                                    sp[6] + bia[col + 6], sp[7] + bia[col + 7]);
            *reinterpret_cast<float4*>(&g_p2[gn * D + col + 0]) = o0;
            *reinterpret_cast<float4*>(&g_p2[gn * D + col + 4]) = o1;
        }
        __syncwarp();
    }
}

// ---------------- final aggregation -> d_out ----------------
// One warp per node; lane owns cols (2*lane, 2*lane+1). Reads layer-2 buffers.
__global__ __launch_bounds__(256) void k_aggr_out(float2* __restrict__ out_arg) {
    const int warp = threadIdx.x >> 5, lane = threadIdx.x & 31;
    const int node = blockIdx.x * 8 + warp;
    if (node >= N_NODES) return;
    const int s0 = g_rp[node], s1 = g_rp[node + 1];

    const __half2* xl = reinterpret_cast<const __half2*>(g_xl2h);

    float2 acc = make_float2(0.f, 0.f);
    int j = s0;
    for (; j + 7 < s1; j += 8) {
        int n[8];
        #pragma unroll
        for (int u = 0; u < 8; u++) n[u] = g_col[j + u];
        float2 v[8];
        #pragma unroll
        for (int u = 0; u < 8; u++) v[u] = __half22float2(xl[n[u] * 32 + lane]);
        acc.x += ((v[0].x + v[1].x) + (v[2].x + v[3].x)) + ((v[4].x + v[5].x) + (v[6].x + v[7].x));
        acc.y += ((v[0].y + v[1].y) + (v[2].y + v[3].y)) + ((v[4].y + v[5].y) + (v[6].y + v[7].y));
    }
    for (; j < s1; j++) {
        const float2 v = __half22float2(xl[g_col[j] * 32 + lane]);
        acc.x += v.x; acc.y += v.y;
    }

    const float inv = g_inv[node];
    const float2 pp = reinterpret_cast<const float2*>(g_p2)[node * 32 + lane];
    float2 r;
    r.x = fmaf(acc.x, inv, pp.x);
    r.y = fmaf(acc.y, inv, pp.y);
    out_arg[node * 32 + lane] = r;
}

// ---------------- launch ----------------
extern "C" void kernel_launch(void* const* d_in, const int* in_sizes, int n_in,
                              void* d_out, int out_size) {
    const float* x   = (const float*)d_in[0];
    const int*   ei  = (const int*)  d_in[1];
    const float* W1l = (const float*)d_in[2];
    const float* b1  = (const float*)d_in[3];
    const float* W1r = (const float*)d_in[4];
    const float* W2l = (const float*)d_in[5];
    const float* b2  = (const float*)d_in[6];
    const float* W2r = (const float*)d_in[7];
    const int* src = ei;
    const int* dst = ei + N_EDGES;

    const int NGRID = (N_NODES + 255) / 256;
    const int E2GRID = (N_EDGES / 2 + 255) / 256;      // 3125
    const int GEMM_GRID = NPAD / 128;                  // 782
    const int AGGR_GRID = (N_NODES + 7) / 8;           // 12500

    // One-time host-side resources (no device memory involved).
    static cudaStream_t s_side = nullptr;
    static cudaEvent_t  ev_fork = nullptr, ev_csr = nullptr, ev_tail = nullptr;
    if (s_side == nullptr) {
        cudaStreamCreateWithFlags(&s_side, cudaStreamNonBlocking);
        cudaEventCreateWithFlags(&ev_fork, cudaEventDisableTiming);
        cudaEventCreateWithFlags(&ev_csr,  cudaEventDisableTiming);
        cudaEventCreateWithFlags(&ev_tail, cudaEventDisableTiming);
    }

    // Fork: CSR build on side stream, concurrent with layer-1 GEMM on main stream.
    cudaEventRecord(ev_fork, 0);
    cudaStreamWaitEvent(s_side, ev_fork, 0);

    k_pos<<<E2GRID, 256, 0, s_side>>>(dst);         // g_deg_i zeroed by prior tail / static init
    k_scan1<<<SCAN_NB, 1024, 0, s_side>>>();
    k_scan3<<<NGRID, 256, 0, s_side>>>();
    k_fill<<<E2GRID, 256, 0, s_side>>>(src, dst);
    cudaEventRecord(ev_csr, s_side);
    k_tail<<<NGRID, 256, 0, s_side>>>();            // re-zero g_deg_i; hidden under k_ag2
    cudaEventRecord(ev_tail, s_side);

    // Main stream: layer-1 GEMM (independent of CSR).
    k_gemm1<<<GEMM_GRID, 256>>>(x, W1l, W1r, b1);

    // Join, then fused layer-1 aggregation + layer-2 GEMM, then final aggregation.
    cudaStreamWaitEvent(0, ev_csr, 0);
    k_ag2<<<GEMM_GRID, 256>>>(W2l, W2r, b2);
    k_aggr_out<<<AGGR_GRID, 256>>>((float2*)d_out);

    // Final join so capture ends with all side-stream work owned by the main stream.
    cudaStreamWaitEvent(0, ev_tail, 0);
}

// round 17
// speedup vs baseline: 1.3519x; 1.3519x over previous
#include <cuda_runtime.h>
#include <cuda_fp16.h>
#include <mma.h>
#include <cstdint>

using namespace nvcuda;

#define N_NODES 100000
#define N_EDGES 1600000
#define D 64
#define NPAD 100096           // 782 * 128, padded node count
#define NHALF 50048           // 391 * 128
#define SCAN_NB 98            // ceil(100000/1024)

// ---------------- static scratch (device-code access ONLY — never passed from host) ----
// Zero-initialized at load; k_tail restores g_deg_i's zeros each launch.
__device__ int   g_deg_i[N_NODES];
__device__ int   g_bsum[128];             // block totals (overwritten every run)
__device__ int   g_rp[N_NODES + 1];       // CSR row pointers (by dst)
__device__ int   g_epos[N_EDGES];         // per-edge within-dst position
__device__ int   g_col[N_EDGES];          // CSR column (src) indices
__device__ float g_inv[N_NODES];
__device__ __align__(16) __half g_h16[NPAD * D];   // layer-1 output, fp16
__device__ __align__(16) __half g_xlh[NPAD * D];   // in @ Wl^T, fp16 (gathered operand)
__device__ __align__(16) float  g_p [NPAD * D];    // in @ Wr^T + b (fp32)

// ---------------- CSR build (round-14 proven versions) ----------------

// Degree count + per-edge slot assignment (atomic return value = position).
__global__ void k_pos(const int* __restrict__ dst) {
    int i = blockIdx.x * blockDim.x + threadIdx.x;
    if (i < N_EDGES / 2) {
        const int2 d = reinterpret_cast<const int2*>(dst)[i];
        const int p0 = atomicAdd(&g_deg_i[d.x], 1);
        const int p1 = atomicAdd(&g_deg_i[d.y], 1);
        reinterpret_cast<int2*>(g_epos)[i] = make_int2(p0, p1);
    }
}

// Block-level inclusive scan (1024 wide); writes rp[i+1] (partial) + block totals.
__global__ __launch_bounds__(1024) void k_scan1() {
    __shared__ int s[1024];
    const int t = threadIdx.x, b = blockIdx.x;
    const int i = b * 1024 + t;
    s[t] = (i < N_NODES) ? g_deg_i[i] : 0;
    __syncthreads();
    for (int off = 1; off < 1024; off <<= 1) {
        int u = (t >= off) ? s[t - off] : 0;
        __syncthreads();
        s[t] += u;
        __syncthreads();
    }
    if (i < N_NODES) g_rp[i + 1] = s[t];
    if (t == 1023) g_bsum[b] = s[t];
}

// Finalize rp (adding inline prefix of block sums, smem-staged) + inv_deg.
__global__ void k_scan3() {
    __shared__ int sb[128];
    const int t = threadIdx.x;
    if (t < 128) sb[t] = g_bsum[t];
    __syncthreads();
    int i = blockIdx.x * blockDim.x + t;
    if (i < N_NODES) {
        const int b = i >> 10;
        int off = 0;
        for (int j = 0; j < b; j++) off += sb[j];   // <=97 smem adds
        g_rp[i + 1] += off;
        g_inv[i] = 1.0f / (float)max(g_deg_i[i], 1);
    }
    if (i == 0) g_rp[0] = 0;
}

// Atomic-free fill: slot = rp[dst] + epos[e].
__global__ void k_fill(const int* __restrict__ src, const int* __restrict__ dst) {
    int i = blockIdx.x * blockDim.x + threadIdx.x;
    if (i < N_EDGES / 2) {
        const int2 s = reinterpret_cast<const int2*>(src)[i];
        const int2 d = reinterpret_cast<const int2*>(dst)[i];
        const int2 p = reinterpret_cast<const int2*>(g_epos)[i];
        g_col[g_rp[d.x] + p.x] = s.x;
        g_col[g_rp[d.y] + p.y] = s.y;
    }
}

// Tail: restore zeroed g_deg_i for the next replay (off the critical path).
__global__ void k_tail() {
    int i = blockIdx.x * blockDim.x + threadIdx.x;
    if (i < N_NODES) g_deg_i[i] = 0;
}

// ---------------- tensor-core dual GEMM ----------------
// xl = in @ Wl^T (fp16 out),  p = in @ Wr^T + b (fp32 out).
// Block: 256 threads = 8 warps; 128-node tile at rbase0 + blockIdx*128.
// LAYER==1: input is fp32 x arg (converted inline); LAYER==2: g_h16.
template <int LAYER>
__global__ __launch_bounds__(256) void k_gemm_tc(const float* __restrict__ xin,
                                                 const float* __restrict__ Wl,
                                                 const float* __restrict__ Wr,
                                                 const float* __restrict__ bia,
                                                 int rbase0) {
    __shared__ __half sw[128 * 72];        // weights: rows 0-63 Wl, 64-127 Wr
    __shared__ __half sx[128 * 72];        // input tile (128 nodes)
    __shared__ float  stage[8][256];       // per-warp 16x16 epilogue staging

    const int tid = threadIdx.x;
    const int rbase = rbase0 + blockIdx.x * 128;

    #pragma unroll
    for (int i = tid; i < 128 * 64; i += 256) {
        const int o = i >> 6, k = i & 63;
        const float w = (o < 64) ? Wl[o * 64 + k] : Wr[(o - 64) * 64 + k];
        sw[o * 72 + k] = __float2half(w);
    }
    if (LAYER == 1) {
        #pragma unroll
        for (int i = tid; i < 128 * 32; i += 256) {    // float2 chunks
            const int r = i >> 5, c2 = i & 31;
            const int gn = rbase + r;
            float2 v = make_float2(0.f, 0.f);
            if (gn < N_NODES) v = reinterpret_cast<const float2*>(xin)[gn * 32 + c2];
            *reinterpret_cast<__half2*>(&sx[r * 72 + c2 * 2]) = __floats2half2_rn(v.x, v.y);
        }
    } else {
        #pragma unroll
        for (int i = tid; i < 128 * 8; i += 256) {     // uint4 = 8 halves
            const int r = i >> 3, c = i & 7;
            const uint4 v = *reinterpret_cast<const uint4*>(&g_h16[(rbase + r) * D + c * 8]);
            *reinterpret_cast<uint4*>(&sx[r * 72 + c * 8]) = v;
        }
    }
    __syncthreads();

    const int warp = tid >> 5;
    const int lane = tid & 31;

    wmma::fragment<wmma::accumulator, 16, 16, 16, float> c[8];
    #pragma unroll
    for (int i = 0; i < 8; i++) wmma::fill_fragment(c[i], 0.f);

    #pragma unroll
    for (int kk = 0; kk < 4; kk++) {
        wmma::fragment<wmma::matrix_a, 16, 16, 16, __half, wmma::row_major> a;
        wmma::load_matrix_sync(a, &sx[warp * 16 * 72 + kk * 16], 72);
        #pragma unroll
        for (int ct = 0; ct < 8; ct++) {
            wmma::fragment<wmma::matrix_b, 16, 16, 16, __half, wmma::col_major> bf;
            wmma::load_matrix_sync(bf, &sw[(ct * 16) * 72 + kk * 16], 72);
            wmma::mma_sync(c[ct], a, bf, c[ct]);
        }
    }

    #pragma unroll
    for (int ct = 0; ct < 8; ct++) {
        wmma::store_matrix_sync(stage[warp], c[ct], 16, wmma::mem_row_major);
        __syncwarp();
        const int r  = lane >> 1;
        const int cc = (lane & 1) * 8;
        const float* sp = &stage[warp][r * 16 + cc];
        const int gn = rbase + warp * 16 + r;
        if (ct < 4) {
            const int col = ct * 16 + cc;
            __half2 h0 = __floats2half2_rn(sp[0], sp[1]);
            __half2 h1 = __floats2half2_rn(sp[2], sp[3]);
            __half2 h2 = __floats2half2_rn(sp[4], sp[5]);
            __half2 h3 = __floats2half2_rn(sp[6], sp[7]);
            uint4 pk;
            pk.x = *reinterpret_cast<uint32_t*>(&h0);
            pk.y = *reinterpret_cast<uint32_t*>(&h1);
            pk.z = *reinterpret_cast<uint32_t*>(&h2);
            pk.w = *reinterpret_cast<uint32_t*>(&h3);
            *reinterpret_cast<uint4*>(&g_xlh[gn * D + col]) = pk;
        } else {
            const int col = (ct - 4) * 16 + cc;
            float4 o0 = make_float4(sp[0] + bia[col + 0], sp[1] + bia[col + 1],
                                    sp[2] + bia[col + 2], sp[3] + bia[col + 3]);
            float4 o1 = make_float4(sp[4] + bia[col + 4], sp[5] + bia[col + 5],
                                    sp[6] + bia[col + 6], sp[7] + bia[col + 7]);
            *reinterpret_cast<float4*>(&g_p[gn * D + col + 0]) = o0;
            *reinterpret_cast<float4*>(&g_p[gn * D + col + 4]) = o1;
        }
        __syncwarp();
    }
}

// ---------------- CSR gather-aggregate + fused epilogue (fp16 gather) ----------------
// One warp per node (node = nbase + ...); lane owns cols (2*lane, 2*lane+1).
// FINAL==0: relu, write g_h16 (fp16).  FINAL==1: no relu, write d_out (fp32).
template <int FINAL>
__global__ __launch_bounds__(256) void k_aggr(float2* __restrict__ out_arg, int nbase) {
    const int warp = threadIdx.x >> 5, lane = threadIdx.x & 31;
    const int node = nbase + blockIdx.x * 8 + warp;
    if (node >= N_NODES) return;
    const int s0 = g_rp[node], s1 = g_rp[node + 1];

    const __half2* xl = reinterpret_cast<const __half2*>(g_xlh);

    float2 acc = make_float2(0.f, 0.f);
    int j = s0;
    for (; j + 7 < s1; j += 8) {
        int n[8];
        #pragma unroll
        for (int u = 0; u < 8; u++) n[u] = g_col[j + u];
        float2 v[8];
        #pragma unroll
        for (int u = 0; u < 8; u++) v[u] = __half22float2(xl[n[u] * 32 + lane]);
        acc.x += ((v[0].x + v[1].x) + (v[2].x + v[3].x)) + ((v[4].x + v[5].x) + (v[6].x + v[7].x));
        acc.y += ((v[0].y + v[1].y) + (v[2].y + v[3].y)) + ((v[4].y + v[5].y) + (v[6].y + v[7].y));
    }
    for (; j < s1; j++) {
        const float2 v = __half22float2(xl[g_col[j] * 32 + lane]);
        acc.x += v.x; acc.y += v.y;
    }

    const float inv = g_inv[node];
    const float2 pp = reinterpret_cast<const float2*>(g_p)[node * 32 + lane];
    float2 r;
    r.x = fmaf(acc.x, inv, pp.x);
    r.y = fmaf(acc.y, inv, pp.y);
    if (FINAL == 0) {
        r.x = fmaxf(r.x, 0.f);
        r.y = fmaxf(r.y, 0.f);
        reinterpret_cast<__half2*>(g_h16)[node * 32 + lane] = __floats2half2_rn(r.x, r.y);
    } else {
        out_arg[node * 32 + lane] = r;
    }
}

// ---------------- launch ----------------
extern "C" void kernel_launch(void* const* d_in, const int* in_sizes, int n_in,
                              void* d_out, int out_size) {
    const float* x   = (const float*)d_in[0];
    const int*   ei  = (const int*)  d_in[1];
    const float* W1l = (const float*)d_in[2];
    const float* b1  = (const float*)d_in[3];
    const float* W1r = (const float*)d_in[4];
    const float* W2l = (const float*)d_in[5];
    const float* b2  = (const float*)d_in[6];
    const float* W2r = (const float*)d_in[7];
    const int* src = ei;
    const int* dst = ei + N_EDGES;

    const int NGRID = (N_NODES + 255) / 256;
    const int E2GRID = (N_EDGES / 2 + 255) / 256;      // 3125
    const int GEMM_GRID  = NPAD / 128;                 // 782 (full)
    const int GEMM_HALF  = NHALF / 128;                // 391
    const int AGGR_GRID  = (N_NODES + 7) / 8;          // 12500 (full)
    const int AGGR_HALF  = NHALF / 8;                  // 6256

    // One-time host-side resources (no device memory involved).
    static cudaStream_t s_side = nullptr;
    static cudaEvent_t  ev_fork = nullptr, ev_csr = nullptr, ev_tail = nullptr;
    static cudaEvent_t  ev_a0A = nullptr, ev_g2A = nullptr;
    if (s_side == nullptr) {
        cudaStreamCreateWithFlags(&s_side, cudaStreamNonBlocking);
        cudaEventCreateWithFlags(&ev_fork, cudaEventDisableTiming);
        cudaEventCreateWithFlags(&ev_csr,  cudaEventDisableTiming);
        cudaEventCreateWithFlags(&ev_tail, cudaEventDisableTiming);
        cudaEventCreateWithFlags(&ev_a0A,  cudaEventDisableTiming);
        cudaEventCreateWithFlags(&ev_g2A,  cudaEventDisableTiming);
    }

    // Fork: CSR build on side stream, concurrent with layer-1 GEMM on main stream.
    cudaEventRecord(ev_fork, 0);
    cudaStreamWaitEvent(s_side, ev_fork, 0);

    k_pos<<<E2GRID, 256, 0, s_side>>>(dst);         // g_deg_i zeroed by prior tail / static init
    k_scan1<<<SCAN_NB, 1024, 0, s_side>>>();
    k_scan3<<<NGRID, 256, 0, s_side>>>();
    k_fill<<<E2GRID, 256, 0, s_side>>>(src, dst);
    cudaEventRecord(ev_csr, s_side);
    k_tail<<<NGRID, 256, 0, s_side>>>();            // re-zero g_deg_i; hidden under aggr0

    // Main stream: layer-1 GEMM (independent of CSR).
    k_gemm_tc<1><<<GEMM_GRID, 256>>>(x, W1l, W1r, b1, 0);

    // Join, then pipelined layer boundary:
    //   aggr0_A -> { aggr0_B (main) || gemm2_A (side) } -> gemm2_B -> aggr1
    cudaStreamWaitEvent(0, ev_csr, 0);
    k_aggr<0><<<AGGR_HALF, 256>>>(nullptr, 0);                       // nodes [0, NHALF)
    cudaEventRecord(ev_a0A, 0);

    cudaStreamWaitEvent(s_side, ev_a0A, 0);
    k_gemm_tc<2><<<GEMM_HALF, 256, 0, s_side>>>(nullptr, W2l, W2r, b2, 0);      // rows [0, NHALF)
    cudaEventRecord(ev_g2A, s_side);

    k_aggr<0><<<AGGR_HALF, 256>>>(nullptr, NHALF);                   // nodes [NHALF, N)
    k_gemm_tc<2><<<GEMM_HALF, 256>>>(nullptr, W2l, W2r, b2, NHALF);  // rows [NHALF, NPAD)

    cudaStreamWaitEvent(0, ev_g2A, 0);
    k_aggr<1><<<AGGR_GRID, 256>>>((float2*)d_out, 0);                // full

    // Final join so capture ends with all side-stream work owned by the main stream.
    cudaEventRecord(ev_tail, s_side);
    cudaStreamWaitEvent(0, ev_tail, 0);
}